// round 1
// baseline (speedup 1.0000x reference)
#include <cuda_runtime.h>
#include <cuda_bf16.h>
#include <math.h>
#include <stdint.h>

// Problem constants
#define B_   32
#define T_   128
#define D_   768
#define A_   512
#define R_   128
#define L_   50
#define BT   (B_ * T_)          // 4096
#define TT   (T_ * T_)          // 16384
#define EN_ELEMS (B_ * L_ * TT) // 26,214,400
#define NLEN 128
#define MAXF 128

// ---------------------------------------------------------------------------
// Scratch (device globals; allocation is forbidden)
// ---------------------------------------------------------------------------
__device__ float g_harc[BT * A_];
__device__ float g_darc[BT * A_];
__device__ float g_marc[BT * A_];
__device__ float g_hlab[BT * R_];
__device__ float g_dlab[BT * R_];
__device__ float g_hl[EN_ELEMS];    // (b,l,i,r)
__device__ float g_labsc[EN_ELEMS]; // (b,l,i,j)
__device__ float g_arc[B_ * TT];
__device__ float g_narc[B_ * TT];
__device__ float g_score[B_ * TT];  // mutated in-place by MST
__device__ int   g_labelid[B_ * TT];
__device__ unsigned char g_oldin[B_ * TT];
__device__ unsigned char g_oldout[B_ * TT];
__device__ unsigned char g_stk_par[B_ * MAXF * NLEN];
__device__ unsigned char g_stk_cyc[B_ * MAXF * NLEN];
__device__ int g_stk_clen[B_ * MAXF];
__device__ unsigned long long g_stk_cons[B_ * MAXF * NLEN * 2];

// ---------------------------------------------------------------------------
// Tiled 128x128 GEMM block (256 threads, 8x8 per-thread microtile, K chunk 16)
// All dims used here are multiples of the tile/chunk sizes — no bounds checks.
// ---------------------------------------------------------------------------
__device__ __forceinline__ void gemm_tile(
    const float* __restrict__ Ag, int lda,     // A tile base (row m0), row-major
    const float* __restrict__ Bg, int ldb,     // B base (see transB)
    int transB,                                 // 0: B[k,n] (pre-offset to col n0); 1: B[n,k] (pre-offset to row n0)
    float* __restrict__ Cg, int ldc,            // C tile base
    int K, const float* __restrict__ biasg, int use_elu)
{
    __shared__ float As[16][128];
    __shared__ float Bs[16][128];
    const int tid = threadIdx.x;
    const int tx = tid & 15;
    const int ty = tid >> 4;
    float acc[8][8];
#pragma unroll
    for (int i = 0; i < 8; i++)
#pragma unroll
        for (int j = 0; j < 8; j++) acc[i][j] = 0.f;

    const int ra = tid >> 2;          // 0..63 (row for transpose loads)
    const int ca = (tid & 3) << 2;    // 0,4,8,12
    const int rb = tid >> 5;          // 0..7
    const int cb = (tid & 31) << 2;   // 0..124

    for (int kc = 0; kc < K; kc += 16) {
        float4 a0 = *(const float4*)(Ag + (size_t)ra * lda + kc + ca);
        float4 a1 = *(const float4*)(Ag + (size_t)(ra + 64) * lda + kc + ca);
        As[ca + 0][ra] = a0.x; As[ca + 1][ra] = a0.y; As[ca + 2][ra] = a0.z; As[ca + 3][ra] = a0.w;
        As[ca + 0][ra + 64] = a1.x; As[ca + 1][ra + 64] = a1.y; As[ca + 2][ra + 64] = a1.z; As[ca + 3][ra + 64] = a1.w;
        if (!transB) {
            float4 b0 = *(const float4*)(Bg + (size_t)(kc + rb) * ldb + cb);
            float4 b1 = *(const float4*)(Bg + (size_t)(kc + rb + 8) * ldb + cb);
            *(float4*)&Bs[rb][cb] = b0;
            *(float4*)&Bs[rb + 8][cb] = b1;
        } else {
            float4 b0 = *(const float4*)(Bg + (size_t)ra * ldb + kc + ca);
            float4 b1 = *(const float4*)(Bg + (size_t)(ra + 64) * ldb + kc + ca);
            Bs[ca + 0][ra] = b0.x; Bs[ca + 1][ra] = b0.y; Bs[ca + 2][ra] = b0.z; Bs[ca + 3][ra] = b0.w;
            Bs[ca + 0][ra + 64] = b1.x; Bs[ca + 1][ra + 64] = b1.y; Bs[ca + 2][ra + 64] = b1.z; Bs[ca + 3][ra + 64] = b1.w;
        }
        __syncthreads();
#pragma unroll
        for (int k = 0; k < 16; k++) {
            float af[8], bf[8];
            *(float4*)(af)     = *(const float4*)&As[k][ty * 8];
            *(float4*)(af + 4) = *(const float4*)&As[k][ty * 8 + 4];
            *(float4*)(bf)     = *(const float4*)&Bs[k][tx * 8];
            *(float4*)(bf + 4) = *(const float4*)&Bs[k][tx * 8 + 4];
#pragma unroll
            for (int i = 0; i < 8; i++)
#pragma unroll
                for (int j = 0; j < 8; j++) acc[i][j] = fmaf(af[i], bf[j], acc[i][j]);
        }
        __syncthreads();
    }
#pragma unroll
    for (int i = 0; i < 8; i++) {
        const int row = ty * 8 + i;
#pragma unroll
        for (int j = 0; j < 8; j++) {
            float v = acc[i][j];
            const int col = tx * 8 + j;
            if (biasg) v += biasg[col];
            if (use_elu) v = (v > 0.f) ? v : expm1f(v);
            Cg[(size_t)row * ldc + col] = v;
        }
    }
}

// C[M,N] = op(A[M,K] @ B[K,N] + bias); grid = (N/128, M/128)
__global__ __launch_bounds__(256) void k_gemm_nn(
    const float* __restrict__ A, const float* __restrict__ Bm,
    const float* __restrict__ bias, float* __restrict__ C,
    int K, int N, int use_elu)
{
    const int m0 = blockIdx.y * 128;
    const int n0 = blockIdx.x * 128;
    gemm_tile(A + (size_t)m0 * K, K, Bm + n0, N, 0,
              C + (size_t)m0 * N + n0, N, K,
              bias ? (bias + n0) : (const float*)0, use_elu);
}

// arc[b,i,j] = sum_a marc[b,i,a] * darc[b,j,a]   (K=512), grid z = b
__global__ __launch_bounds__(256) void k_arc_nt()
{
    const int b = blockIdx.z;
    gemm_tile(g_marc + (size_t)b * T_ * A_, A_,
              g_darc + (size_t)b * T_ * A_, A_, 1,
              g_arc + (size_t)b * TT, T_, A_, (const float*)0, 0);
}

// hl[b,l,i,s] = sum_r hlab[b,i,r] * Ulab[l,r,s]   grid z = b*50+l
__global__ __launch_bounds__(256) void k_hl(const float* __restrict__ Ulab)
{
    const int z = blockIdx.z;
    const int b = z / L_;
    const int l = z - b * L_;
    gemm_tile(g_hlab + (size_t)b * T_ * R_, R_,
              Ulab + (size_t)l * R_ * R_, R_, 0,
              g_hl + (size_t)z * TT, T_, R_, (const float*)0, 0);
}

// labsc[b,l,i,j] = sum_s hl[b,l,i,s] * dlab[b,j,s]   grid z = b*50+l
__global__ __launch_bounds__(256) void k_lab_nt()
{
    const int z = blockIdx.z;
    const int b = z / L_;
    gemm_tile(g_hl + (size_t)z * TT, T_,
              g_dlab + (size_t)b * T_ * R_, R_, 1,
              g_labsc + (size_t)z * TT, T_, R_, (const float*)0, 0);
}

// norm_arc: log_softmax over heads (axis i) per (b, j)
__global__ void k_norm_arc()
{
    const int b = blockIdx.x;
    const int j = threadIdx.x;
    const float* base = g_arc + (size_t)b * TT;
    float m = -3.4e38f;
#pragma unroll 8
    for (int i = 0; i < T_; i++) m = fmaxf(m, base[i * T_ + j]);
    float s = 0.f;
#pragma unroll 8
    for (int i = 0; i < T_; i++) s += expf(base[i * T_ + j] - m);
    const float ls = logf(s);
    float* nb = g_narc + (size_t)b * TT;
#pragma unroll 8
    for (int i = 0; i < T_; i++) nb[i * T_ + j] = (base[i * T_ + j] - m) - ls;
}

// energy[b,l,i,j] = exp(narc[b,i,j] + log_softmax_l(labsc)[b,l,i,j])
// also score[b,i,j] = max_l energy (diag zeroed), labelid = argmax_l
__global__ void k_energy(float* __restrict__ energy)
{
    const int bi = blockIdx.x;
    const int b = bi >> 7;
    const int i = bi & 127;
    const int j = threadIdx.x;
    const size_t base = (size_t)b * (L_ * TT) + (size_t)i * T_ + j;
    float m = -3.4e38f;
#pragma unroll 5
    for (int l = 0; l < L_; l++) m = fmaxf(m, g_labsc[base + (size_t)l * TT]);
    float s = 0.f;
#pragma unroll 5
    for (int l = 0; l < L_; l++) s += expf(g_labsc[base + (size_t)l * TT] - m);
    const float ls = logf(s);
    const float na = g_narc[(size_t)b * TT + i * T_ + j];
    float best = -3.4e38f;
    int arg = 0;
#pragma unroll 5
    for (int l = 0; l < L_; l++) {
        const float x = g_labsc[base + (size_t)l * TT];
        const float e = expf(na + ((x - m) - ls));
        energy[base + (size_t)l * TT] = e;
        if (e > best) { best = e; arg = l; }
    }
    g_score[(size_t)b * TT + i * T_ + j] = (i == j) ? 0.f : best;
    g_labelid[(size_t)b * TT + i * T_ + j] = arg;
}

// ---------------------------------------------------------------------------
// Chu-Liu-Edmonds MST (one block per batch, iterative with explicit stack)
// ---------------------------------------------------------------------------
__global__ __launch_bounds__(128) void k_mst(float* __restrict__ out, int has_tail)
{
    const int b = blockIdx.x;
    const int tid = threadIdx.x;
    float* S = g_score + (size_t)b * TT;
    unsigned char* OI = g_oldin + (size_t)b * TT;
    unsigned char* OO = g_oldout + (size_t)b * TT;

    __shared__ int s_par[NLEN];
    __shared__ unsigned char s_cur[NLEN];
    __shared__ unsigned char s_incyc[NLEN];
    __shared__ unsigned char s_added[NLEN];
    __shared__ int s_cyc[NLEN];
    __shared__ int s_final[NLEN];
    __shared__ unsigned long long s_repA[NLEN], s_repB[NLEN];
    __shared__ int s_clen, s_has, s_depth;
    __shared__ float s_cw;

    for (int idx = tid; idx < TT; idx += NLEN) {
        const int i = idx >> 7, j = idx & 127;
        OI[idx] = (unsigned char)((i == j) ? 0 : i);
        OO[idx] = (unsigned char)((i == j) ? 0 : j);
    }
    s_cur[tid] = 1;
    s_repA[tid] = (tid < 64) ? (1ull << tid) : 0ull;
    s_repB[tid] = (tid >= 64) ? (1ull << (tid - 64)) : 0ull;
    s_final[tid] = -2;
    if (tid == 0) s_depth = 0;
    __syncthreads();

    while (true) {
        // --- parents: argmax head for each current node (parallel over nodes) ---
        if (tid == 0) {
            s_par[0] = -1;
        } else {
            int par = 0;
            if (s_cur[tid]) {
                float best = S[tid]; // score[0, tid]
                for (int n2 = 1; n2 < NLEN; n2++) {
                    if (n2 != tid && s_cur[n2]) {
                        const float v = S[n2 * NLEN + tid];
                        if (v > best) { best = v; par = n2; }
                    }
                }
            }
            s_par[tid] = par;
        }
        __syncthreads();

        // --- cycle detection (serial, thread 0) ---
        if (tid == 0) {
            for (int i = 0; i < NLEN; i++) s_added[i] = 0;
            s_added[0] = 1;
            int has = 0, clen = 0;
            for (int i = 1; i < NLEN; i++) {
                if (s_added[i] || !s_cur[i]) continue;
                unsigned long long t0 = 0, t1 = 0;
                if (i < 64) t0 |= 1ull << i; else t1 |= 1ull << (i - 64);
                s_added[i] = 1;
                has = 1;
                int next = i;
                while (true) {
                    const int p = s_par[next];
                    const int inc = (p < 64) ? (int)((t0 >> p) & 1ull)
                                             : (int)((t1 >> (p - 64)) & 1ull);
                    if (inc) break;
                    next = p;
                    if (s_added[next]) { has = 0; break; }
                    s_added[next] = 1;
                    if (next < 64) t0 |= 1ull << next; else t1 |= 1ull << (next - 64);
                }
                if (has) {
                    clen = 0;
                    s_cyc[clen++] = next;        // "original"
                    int n2 = s_par[next];
                    while (n2 != next) { s_cyc[clen++] = n2; n2 = s_par[n2]; }
                    break;
                }
            }
            s_has = has; s_clen = clen;
            if (has) {
                float cw = 0.f;
                for (int c = 0; c < clen; c++) {
                    const int v = s_cyc[c];
                    cw += S[s_par[v] * NLEN + v];
                }
                s_cw = cw;
            }
        }
        __syncthreads();
        if (!s_has) break;

        const int clen = s_clen;
        const int rep = s_cyc[0];
        const float cw = s_cw;
        s_incyc[tid] = 0;
        __syncthreads();
        if (tid < clen) s_incyc[s_cyc[tid]] = 1;
        __syncthreads();

        // --- contraction updates (parallel over outside nodes) ---
        if (s_cur[tid] && !s_incyc[tid]) {
            const int node = tid;
            float inw = -3.4e38f, outw = -3.4e38f;
            int ine = -1, oute = -1;
            for (int c = 0; c < clen; c++) {
                const int v = s_cyc[c];
                const float sv = S[v * NLEN + node];
                if (sv > inw) { inw = sv; ine = v; }
                const float so = cw + S[node * NLEN + v] - S[s_par[v] * NLEN + v];
                if (so > outw) { outw = so; oute = v; }
            }
            S[rep * NLEN + node] = inw;
            OI[rep * NLEN + node] = OI[ine * NLEN + node];
            OO[rep * NLEN + node] = OO[ine * NLEN + node];
            S[node * NLEN + rep] = outw;
            OO[node * NLEN + rep] = OO[node * NLEN + oute];
            OI[node * NLEN + rep] = OI[node * NLEN + oute];
        }
        __syncthreads();

        // --- push stack frame ---
        const int d = s_depth;
        g_stk_par[((size_t)b * MAXF + d) * NLEN + tid] = (unsigned char)s_par[tid];
        if (tid < clen) g_stk_cyc[((size_t)b * MAXF + d) * NLEN + tid] = (unsigned char)s_cyc[tid];
        __syncthreads();
        if (tid == 0) {
            g_stk_clen[b * MAXF + d] = clen;
            for (int c = 0; c < clen; c++) {
                const int v = s_cyc[c];
                const unsigned long long a0 = s_repA[v], a1 = s_repB[v];
                const size_t ci = (((size_t)b * MAXF + d) * NLEN + c) * 2;
                g_stk_cons[ci] = a0;
                g_stk_cons[ci + 1] = a1;
                if (c > 0) {
                    s_cur[v] = 0;
                    s_repA[rep] |= a0;
                    s_repB[rep] |= a1;
                }
            }
            s_depth = d + 1;
        }
        __syncthreads();
    }

    // --- base case + unwind (serial, thread 0) ---
    if (tid == 0) {
        s_final[0] = -1;
        for (int node = 1; node < NLEN; node++) {
            if (!s_cur[node]) continue;
            const int p = s_par[node];
            const int parent = OI[p * NLEN + node];
            const int child = OO[p * NLEN + node];
            s_final[child] = parent;
        }
        for (int d = s_depth - 1; d >= 0; d--) {
            const int clen = g_stk_clen[b * MAXF + d];
            const unsigned char* par = &g_stk_par[((size_t)b * MAXF + d) * NLEN];
            const unsigned char* cyc = &g_stk_cyc[((size_t)b * MAXF + d) * NLEN];
            unsigned long long f0 = 0, f1 = 0;
            for (int x = 0; x < NLEN; x++)
                if (s_final[x] != -2) {
                    if (x < 64) f0 |= 1ull << x; else f1 |= 1ull << (x - 64);
                }
            int key = -1;
            for (int c = 0; c < clen; c++) {
                const size_t ci = (((size_t)b * MAXF + d) * NLEN + c) * 2;
                if ((g_stk_cons[ci] & f0) | (g_stk_cons[ci + 1] & f1)) { key = cyc[c]; break; }
            }
            if (key < 0) continue;  // should not happen
            int prev = par[key];
            while (prev != key) {
                const int pp = par[prev];
                const int child = OO[pp * NLEN + prev];
                const int parent = OI[pp * NLEN + prev];
                s_final[child] = parent;
                prev = pp;
            }
        }
    }
    __syncthreads();

    if (has_tail) {
        float hv = 0.f, tv = 1.f;
        const int fe = s_final[tid];
        if (fe != -2) {
            hv = (float)fe;
            const int row = (fe < 0) ? (NLEN - 1) : fe;  // python negative indexing
            tv = (float)g_labelid[(size_t)b * TT + row * NLEN + tid];
        }
        out[(size_t)EN_ELEMS + b * NLEN + tid] = hv;
        out[(size_t)EN_ELEMS + B_ * NLEN + b * NLEN + tid] = tv;
    }
}

// ---------------------------------------------------------------------------
// Launch
// ---------------------------------------------------------------------------
extern "C" void kernel_launch(void* const* d_in, const int* in_sizes, int n_in,
                              void* d_out, int out_size)
{
    const float* X    = (const float*)d_in[0];
    const float* Wha  = (const float*)d_in[1];
    const float* bha  = (const float*)d_in[2];
    const float* Wda  = (const float*)d_in[3];
    const float* bda  = (const float*)d_in[4];
    const float* Uarc = (const float*)d_in[5];
    const float* Whl  = (const float*)d_in[6];
    const float* bhl  = (const float*)d_in[7];
    const float* Wdl  = (const float*)d_in[8];
    const float* bdl  = (const float*)d_in[9];
    const float* Ulab = (const float*)d_in[10];
    float* out = (float*)d_out;

    void* p;
    cudaGetSymbolAddress(&p, g_harc); float* harc = (float*)p;
    cudaGetSymbolAddress(&p, g_darc); float* darc = (float*)p;
    cudaGetSymbolAddress(&p, g_marc); float* marc = (float*)p;
    cudaGetSymbolAddress(&p, g_hlab); float* hlab = (float*)p;
    cudaGetSymbolAddress(&p, g_dlab); float* dlab = (float*)p;

    const int has_tail = (out_size >= EN_ELEMS + 2 * B_ * T_);

    // Projections: elu(X @ W + b)
    k_gemm_nn<<<dim3(A_ / 128, BT / 128), 256>>>(X, Wha, bha, harc, D_, A_, 1);
    k_gemm_nn<<<dim3(A_ / 128, BT / 128), 256>>>(X, Wda, bda, darc, D_, A_, 1);
    k_gemm_nn<<<dim3(R_ / 128, BT / 128), 256>>>(X, Whl, bhl, hlab, D_, R_, 1);
    k_gemm_nn<<<dim3(R_ / 128, BT / 128), 256>>>(X, Wdl, bdl, dlab, D_, R_, 1);

    // marc = harc @ U_arc
    k_gemm_nn<<<dim3(A_ / 128, BT / 128), 256>>>(harc, Uarc, (const float*)0, marc, A_, A_, 0);

    // arc_scores[b] = marc[b] @ darc[b]^T
    k_arc_nt<<<dim3(1, 1, B_), 256>>>();

    // hl[b,l] = hlab[b] @ Ulab[l];  labsc[b,l] = hl[b,l] @ dlab[b]^T
    k_hl<<<dim3(1, 1, B_ * L_), 256>>>(Ulab);
    k_lab_nt<<<dim3(1, 1, B_ * L_), 256>>>();

    // softmaxes + energy + score/label matrices
    k_norm_arc<<<B_, T_>>>();
    k_energy<<<B_ * T_, T_>>>(out);

    // MST decode -> heads/tags tail
    k_mst<<<B_, NLEN>>>(out, has_tail);
}

// round 2
// speedup vs baseline: 1.2324x; 1.2324x over previous
#include <cuda_runtime.h>
#include <cuda_bf16.h>
#include <math.h>
#include <stdint.h>

// Problem constants
#define B_   32
#define T_   128
#define D_   768
#define A_   512
#define R_   128
#define L_   50
#define NP   1280               // packed projection width: 512+512+128+128
#define BT   (B_ * T_)          // 4096
#define TT   (T_ * T_)          // 16384
#define EN_ELEMS (B_ * L_ * TT) // 26,214,400
#define NLEN 128
#define MAXF 128

// ---------------------------------------------------------------------------
// Scratch (device globals; allocation is forbidden)
// ---------------------------------------------------------------------------
__device__ float g_Wp[D_ * NP];     // packed projection weights
__device__ float g_bp[NP];          // packed bias
__device__ float g_proj[BT * NP];   // packed elu(X@W+b): [harc|darc|hlab|dlab]
__device__ float g_marc[BT * A_];
__device__ float g_labsc[EN_ELEMS]; // (b,l,i,j)
__device__ float g_arc[B_ * TT];
__device__ float g_narc[B_ * TT];
__device__ float g_score[B_ * TT];  // mutated in-place by MST
__device__ int   g_labelid[B_ * TT];
__device__ unsigned char g_oldin[B_ * TT];
__device__ unsigned char g_oldout[B_ * TT];
__device__ unsigned char g_stk_par[B_ * MAXF * NLEN];
__device__ unsigned char g_stk_cyc[B_ * MAXF * NLEN];
__device__ int g_stk_clen[B_ * MAXF];
__device__ unsigned long long g_stk_cons[B_ * MAXF * NLEN * 2];

// column offsets inside packed proj
#define OFF_HARC 0
#define OFF_DARC 512
#define OFF_HLAB 1024
#define OFF_DLAB 1152

// ---------------------------------------------------------------------------
// Weight/bias packing
// ---------------------------------------------------------------------------
__global__ void k_pack(const float* __restrict__ Wha, const float* __restrict__ Wda,
                       const float* __restrict__ Whl, const float* __restrict__ Wdl,
                       const float* __restrict__ bha, const float* __restrict__ bda,
                       const float* __restrict__ bhl, const float* __restrict__ bdl)
{
    const int idx = blockIdx.x * 256 + threadIdx.x;
    if (idx < D_ * NP) {
        const int k = idx / NP;
        const int n = idx - k * NP;
        float v;
        if (n < 512)       v = Wha[k * 512 + n];
        else if (n < 1024) v = Wda[k * 512 + (n - 512)];
        else if (n < 1152) v = Whl[k * 128 + (n - 1024)];
        else               v = Wdl[k * 128 + (n - 1152)];
        g_Wp[idx] = v;
    }
    if (idx < NP) {
        float v;
        if (idx < 512)       v = bha[idx];
        else if (idx < 1024) v = bda[idx - 512];
        else if (idx < 1152) v = bhl[idx - 1024];
        else                 v = bdl[idx - 1152];
        g_bp[idx] = v;
    }
}

// ---------------------------------------------------------------------------
// Tiled 128x128 GEMM block (256 threads, 8x8 microtile, K chunk 16)
// ---------------------------------------------------------------------------
__device__ __forceinline__ void gemm_tile(
    const float* __restrict__ Ag, int lda,
    const float* __restrict__ Bg, int ldb, int transB,
    float* __restrict__ Cg, int ldc,
    int K, const float* __restrict__ biasg, int use_elu)
{
    __shared__ float As[16][128];
    __shared__ float Bs[16][128];
    const int tid = threadIdx.x;
    const int tx = tid & 15;
    const int ty = tid >> 4;
    float acc[8][8];
#pragma unroll
    for (int i = 0; i < 8; i++)
#pragma unroll
        for (int j = 0; j < 8; j++) acc[i][j] = 0.f;

    const int ra = tid >> 2;
    const int ca = (tid & 3) << 2;
    const int rb = tid >> 5;
    const int cb = (tid & 31) << 2;

    for (int kc = 0; kc < K; kc += 16) {
        float4 a0 = *(const float4*)(Ag + (size_t)ra * lda + kc + ca);
        float4 a1 = *(const float4*)(Ag + (size_t)(ra + 64) * lda + kc + ca);
        As[ca + 0][ra] = a0.x; As[ca + 1][ra] = a0.y; As[ca + 2][ra] = a0.z; As[ca + 3][ra] = a0.w;
        As[ca + 0][ra + 64] = a1.x; As[ca + 1][ra + 64] = a1.y; As[ca + 2][ra + 64] = a1.z; As[ca + 3][ra + 64] = a1.w;
        if (!transB) {
            float4 b0 = *(const float4*)(Bg + (size_t)(kc + rb) * ldb + cb);
            float4 b1 = *(const float4*)(Bg + (size_t)(kc + rb + 8) * ldb + cb);
            *(float4*)&Bs[rb][cb] = b0;
            *(float4*)&Bs[rb + 8][cb] = b1;
        } else {
            float4 b0 = *(const float4*)(Bg + (size_t)ra * ldb + kc + ca);
            float4 b1 = *(const float4*)(Bg + (size_t)(ra + 64) * ldb + kc + ca);
            Bs[ca + 0][ra] = b0.x; Bs[ca + 1][ra] = b0.y; Bs[ca + 2][ra] = b0.z; Bs[ca + 3][ra] = b0.w;
            Bs[ca + 0][ra + 64] = b1.x; Bs[ca + 1][ra + 64] = b1.y; Bs[ca + 2][ra + 64] = b1.z; Bs[ca + 3][ra + 64] = b1.w;
        }
        __syncthreads();
#pragma unroll
        for (int k = 0; k < 16; k++) {
            float af[8], bf[8];
            *(float4*)(af)     = *(const float4*)&As[k][ty * 8];
            *(float4*)(af + 4) = *(const float4*)&As[k][ty * 8 + 4];
            *(float4*)(bf)     = *(const float4*)&Bs[k][tx * 8];
            *(float4*)(bf + 4) = *(const float4*)&Bs[k][tx * 8 + 4];
#pragma unroll
            for (int i = 0; i < 8; i++)
#pragma unroll
                for (int j = 0; j < 8; j++) acc[i][j] = fmaf(af[i], bf[j], acc[i][j]);
        }
        __syncthreads();
    }
#pragma unroll
    for (int i = 0; i < 8; i++) {
        const int row = ty * 8 + i;
#pragma unroll
        for (int j = 0; j < 8; j++) {
            float v = acc[i][j];
            const int col = tx * 8 + j;
            if (biasg) v += biasg[col];
            if (use_elu) v = (v > 0.f) ? v : expm1f(v);
            Cg[(size_t)row * ldc + col] = v;
        }
    }
}

// generic NN GEMM: C[M,N] = op(A[M,K](lda) @ B[K,N] + bias)
__global__ __launch_bounds__(256, 2) void k_gemm_nn(
    const float* __restrict__ A, int lda, const float* __restrict__ Bm,
    const float* __restrict__ bias, float* __restrict__ C,
    int K, int N, int use_elu)
{
    const int m0 = blockIdx.y * 128;
    const int n0 = blockIdx.x * 128;
    gemm_tile(A + (size_t)m0 * lda, lda, Bm + n0, N, 0,
              C + (size_t)m0 * N + n0, N, K,
              bias ? (bias + n0) : (const float*)0, use_elu);
}

// ---------------------------------------------------------------------------
// arc[b,i,j] = sum_a marc[b,i,a] * darc[b,j,a]  — 64x64 tiles, grid (2,2,32)
// ---------------------------------------------------------------------------
__global__ __launch_bounds__(256, 4) void k_arc64()
{
    const int b = blockIdx.z;
    const int m0 = blockIdx.y * 64;
    const int n0 = blockIdx.x * 64;
    const float* Ag = g_marc + (size_t)b * T_ * A_ + (size_t)m0 * A_;
    const float* Bg = g_proj + (size_t)b * T_ * NP + (size_t)n0 * NP + OFF_DARC;

    __shared__ float As[16][64];
    __shared__ float Bs[16][64];
    const int tid = threadIdx.x;
    const int tx = tid & 15;
    const int ty = tid >> 4;
    const int ra = tid >> 2;          // 0..63
    const int ca = (tid & 3) << 2;

    float acc[4][4];
#pragma unroll
    for (int i = 0; i < 4; i++)
#pragma unroll
        for (int j = 0; j < 4; j++) acc[i][j] = 0.f;

    for (int kc = 0; kc < A_; kc += 16) {
        float4 a0 = *(const float4*)(Ag + (size_t)ra * A_ + kc + ca);
        float4 b0 = *(const float4*)(Bg + (size_t)ra * NP + kc + ca);
        As[ca + 0][ra] = a0.x; As[ca + 1][ra] = a0.y; As[ca + 2][ra] = a0.z; As[ca + 3][ra] = a0.w;
        Bs[ca + 0][ra] = b0.x; Bs[ca + 1][ra] = b0.y; Bs[ca + 2][ra] = b0.z; Bs[ca + 3][ra] = b0.w;
        __syncthreads();
#pragma unroll
        for (int k = 0; k < 16; k++) {
            float af[4], bf[4];
            *(float4*)af = *(const float4*)&As[k][ty * 4];
            *(float4*)bf = *(const float4*)&Bs[k][tx * 4];
#pragma unroll
            for (int i = 0; i < 4; i++)
#pragma unroll
                for (int j = 0; j < 4; j++) acc[i][j] = fmaf(af[i], bf[j], acc[i][j]);
        }
        __syncthreads();
    }
    float* C = g_arc + (size_t)b * TT + (size_t)(m0 + ty * 4) * T_ + n0 + tx * 4;
#pragma unroll
    for (int i = 0; i < 4; i++)
        *(float4*)(C + (size_t)i * T_) = make_float4(acc[i][0], acc[i][1], acc[i][2], acc[i][3]);
}

// ---------------------------------------------------------------------------
// Fused label path: per (b,l): tmp = hlab[b] @ Ulab[l] (smem), labsc = tmp @ dlab[b]^T
// dynamic smem: As(16x128) + Bs(16x128) + Tmp(128x128) = 80KB
// ---------------------------------------------------------------------------
__global__ __launch_bounds__(256) void k_lab_fused(const float* __restrict__ Ulab)
{
    extern __shared__ float sm[];
    float (*As)[128] = (float (*)[128])sm;
    float (*Bs)[128] = (float (*)[128])(sm + 2048);
    float* Tmp = sm + 4096;

    const int z = blockIdx.x;
    const int b = z / L_;
    const int l = z - b * L_;
    const float* hlab = g_proj + (size_t)b * T_ * NP + OFF_HLAB;
    const float* dlab = g_proj + (size_t)b * T_ * NP + OFF_DLAB;
    const float* U = Ulab + (size_t)l * R_ * R_;

    const int tid = threadIdx.x;
    const int tx = tid & 15;
    const int ty = tid >> 4;
    const int ra = tid >> 2;
    const int ca = (tid & 3) << 2;
    const int rb = tid >> 5;
    const int cb = (tid & 31) << 2;

    float acc[8][8];
#pragma unroll
    for (int i = 0; i < 8; i++)
#pragma unroll
        for (int j = 0; j < 8; j++) acc[i][j] = 0.f;

    // phase 1: tmp = hlab @ U   (K = 128)
    for (int kc = 0; kc < R_; kc += 16) {
        float4 a0 = *(const float4*)(hlab + (size_t)ra * NP + kc + ca);
        float4 a1 = *(const float4*)(hlab + (size_t)(ra + 64) * NP + kc + ca);
        As[ca + 0][ra] = a0.x; As[ca + 1][ra] = a0.y; As[ca + 2][ra] = a0.z; As[ca + 3][ra] = a0.w;
        As[ca + 0][ra + 64] = a1.x; As[ca + 1][ra + 64] = a1.y; As[ca + 2][ra + 64] = a1.z; As[ca + 3][ra + 64] = a1.w;
        float4 b0 = *(const float4*)(U + (size_t)(kc + rb) * R_ + cb);
        float4 b1 = *(const float4*)(U + (size_t)(kc + rb + 8) * R_ + cb);
        *(float4*)&Bs[rb][cb] = b0;
        *(float4*)&Bs[rb + 8][cb] = b1;
        __syncthreads();
#pragma unroll
        for (int k = 0; k < 16; k++) {
            float af[8], bf[8];
            *(float4*)(af)     = *(const float4*)&As[k][ty * 8];
            *(float4*)(af + 4) = *(const float4*)&As[k][ty * 8 + 4];
            *(float4*)(bf)     = *(const float4*)&Bs[k][tx * 8];
            *(float4*)(bf + 4) = *(const float4*)&Bs[k][tx * 8 + 4];
#pragma unroll
            for (int i = 0; i < 8; i++)
#pragma unroll
                for (int j = 0; j < 8; j++) acc[i][j] = fmaf(af[i], bf[j], acc[i][j]);
        }
        __syncthreads();
    }
    // write tmp to smem
#pragma unroll
    for (int i = 0; i < 8; i++) {
        const int row = ty * 8 + i;
        *(float4*)&Tmp[row * 128 + tx * 8]     = make_float4(acc[i][0], acc[i][1], acc[i][2], acc[i][3]);
        *(float4*)&Tmp[row * 128 + tx * 8 + 4] = make_float4(acc[i][4], acc[i][5], acc[i][6], acc[i][7]);
    }
    __syncthreads();

    // phase 2: labsc = Tmp @ dlab^T   (K = 128)
#pragma unroll
    for (int i = 0; i < 8; i++)
#pragma unroll
        for (int j = 0; j < 8; j++) acc[i][j] = 0.f;

    for (int kc = 0; kc < R_; kc += 16) {
        float4 b0 = *(const float4*)(dlab + (size_t)ra * NP + kc + ca);
        float4 b1 = *(const float4*)(dlab + (size_t)(ra + 64) * NP + kc + ca);
        Bs[ca + 0][ra] = b0.x; Bs[ca + 1][ra] = b0.y; Bs[ca + 2][ra] = b0.z; Bs[ca + 3][ra] = b0.w;
        Bs[ca + 0][ra + 64] = b1.x; Bs[ca + 1][ra + 64] = b1.y; Bs[ca + 2][ra + 64] = b1.z; Bs[ca + 3][ra + 64] = b1.w;
        __syncthreads();
#pragma unroll
        for (int k = 0; k < 16; k++) {
            float af[8], bf[8];
#pragma unroll
            for (int i = 0; i < 8; i++) af[i] = Tmp[(ty * 8 + i) * 128 + kc + k];
            *(float4*)(bf)     = *(const float4*)&Bs[k][tx * 8];
            *(float4*)(bf + 4) = *(const float4*)&Bs[k][tx * 8 + 4];
#pragma unroll
            for (int i = 0; i < 8; i++)
#pragma unroll
                for (int j = 0; j < 8; j++) acc[i][j] = fmaf(af[i], bf[j], acc[i][j]);
        }
        __syncthreads();
    }
    float* out = g_labsc + (size_t)z * TT;
#pragma unroll
    for (int i = 0; i < 8; i++) {
        const int row = ty * 8 + i;
        *(float4*)(out + (size_t)row * T_ + tx * 8)     = make_float4(acc[i][0], acc[i][1], acc[i][2], acc[i][3]);
        *(float4*)(out + (size_t)row * T_ + tx * 8 + 4) = make_float4(acc[i][4], acc[i][5], acc[i][6], acc[i][7]);
    }
}

// norm_arc: log_softmax over heads (axis i) per (b, j)
__global__ void k_norm_arc()
{
    const int b = blockIdx.x;
    const int j = threadIdx.x;
    const float* base = g_arc + (size_t)b * TT;
    float m = -3.4e38f;
#pragma unroll 8
    for (int i = 0; i < T_; i++) m = fmaxf(m, base[i * T_ + j]);
    float s = 0.f;
#pragma unroll 8
    for (int i = 0; i < T_; i++) s += expf(base[i * T_ + j] - m);
    const float ls = logf(s);
    float* nb = g_narc + (size_t)b * TT;
#pragma unroll 8
    for (int i = 0; i < T_; i++) nb[i * T_ + j] = (base[i * T_ + j] - m) - ls;
}

// energy[b,l,i,j] = exp(narc[b,i,j] + log_softmax_l(labsc)[b,l,i,j])
__global__ void k_energy(float* __restrict__ energy)
{
    const int bi = blockIdx.x;
    const int b = bi >> 7;
    const int i = bi & 127;
    const int j = threadIdx.x;
    const size_t base = (size_t)b * (L_ * TT) + (size_t)i * T_ + j;
    float m = -3.4e38f;
#pragma unroll 5
    for (int l = 0; l < L_; l++) m = fmaxf(m, g_labsc[base + (size_t)l * TT]);
    float s = 0.f;
#pragma unroll 5
    for (int l = 0; l < L_; l++) s += expf(g_labsc[base + (size_t)l * TT] - m);
    const float ls = logf(s);
    const float na = g_narc[(size_t)b * TT + i * T_ + j];
    float best = -3.4e38f;
    int arg = 0;
#pragma unroll 5
    for (int l = 0; l < L_; l++) {
        const float x = g_labsc[base + (size_t)l * TT];
        const float e = expf(na + ((x - m) - ls));
        energy[base + (size_t)l * TT] = e;
        if (e > best) { best = e; arg = l; }
    }
    g_score[(size_t)b * TT + i * T_ + j] = (i == j) ? 0.f : best;
    g_labelid[(size_t)b * TT + i * T_ + j] = arg;
}

// ---------------------------------------------------------------------------
// Chu-Liu-Edmonds MST (one block per batch, iterative with explicit stack)
// ---------------------------------------------------------------------------
__global__ __launch_bounds__(128) void k_mst(float* __restrict__ out, int has_tail)
{
    const int b = blockIdx.x;
    const int tid = threadIdx.x;
    float* S = g_score + (size_t)b * TT;
    unsigned char* OI = g_oldin + (size_t)b * TT;
    unsigned char* OO = g_oldout + (size_t)b * TT;

    __shared__ int s_par[NLEN];
    __shared__ unsigned char s_cur[NLEN];
    __shared__ unsigned char s_incyc[NLEN];
    __shared__ unsigned char s_added[NLEN];
    __shared__ int s_cyc[NLEN];
    __shared__ int s_final[NLEN];
    __shared__ unsigned long long s_repA[NLEN], s_repB[NLEN];
    __shared__ int s_clen, s_has, s_depth;
    __shared__ float s_cw;

    for (int idx = tid; idx < TT; idx += NLEN) {
        const int i = idx >> 7, j = idx & 127;
        OI[idx] = (unsigned char)((i == j) ? 0 : i);
        OO[idx] = (unsigned char)((i == j) ? 0 : j);
    }
    s_cur[tid] = 1;
    s_repA[tid] = (tid < 64) ? (1ull << tid) : 0ull;
    s_repB[tid] = (tid >= 64) ? (1ull << (tid - 64)) : 0ull;
    s_final[tid] = -2;
    if (tid == 0) s_depth = 0;
    __syncthreads();

    while (true) {
        if (tid == 0) {
            s_par[0] = -1;
        } else {
            int par = 0;
            if (s_cur[tid]) {
                float best = S[tid];
                for (int n2 = 1; n2 < NLEN; n2++) {
                    if (n2 != tid && s_cur[n2]) {
                        const float v = S[n2 * NLEN + tid];
                        if (v > best) { best = v; par = n2; }
                    }
                }
            }
            s_par[tid] = par;
        }
        __syncthreads();

        if (tid == 0) {
            for (int i = 0; i < NLEN; i++) s_added[i] = 0;
            s_added[0] = 1;
            int has = 0, clen = 0;
            for (int i = 1; i < NLEN; i++) {
                if (s_added[i] || !s_cur[i]) continue;
                unsigned long long t0 = 0, t1 = 0;
                if (i < 64) t0 |= 1ull << i; else t1 |= 1ull << (i - 64);
                s_added[i] = 1;
                has = 1;
                int next = i;
                while (true) {
                    const int p = s_par[next];
                    const int inc = (p < 64) ? (int)((t0 >> p) & 1ull)
                                             : (int)((t1 >> (p - 64)) & 1ull);
                    if (inc) break;
                    next = p;
                    if (s_added[next]) { has = 0; break; }
                    s_added[next] = 1;
                    if (next < 64) t0 |= 1ull << next; else t1 |= 1ull << (next - 64);
                }
                if (has) {
                    clen = 0;
                    s_cyc[clen++] = next;
                    int n2 = s_par[next];
                    while (n2 != next) { s_cyc[clen++] = n2; n2 = s_par[n2]; }
                    break;
                }
            }
            s_has = has; s_clen = clen;
            if (has) {
                float cw = 0.f;
                for (int c = 0; c < clen; c++) {
                    const int v = s_cyc[c];
                    cw += S[s_par[v] * NLEN + v];
                }
                s_cw = cw;
            }
        }
        __syncthreads();
        if (!s_has) break;

        const int clen = s_clen;
        const int rep = s_cyc[0];
        const float cw = s_cw;
        s_incyc[tid] = 0;
        __syncthreads();
        if (tid < clen) s_incyc[s_cyc[tid]] = 1;
        __syncthreads();

        if (s_cur[tid] && !s_incyc[tid]) {
            const int node = tid;
            float inw = -3.4e38f, outw = -3.4e38f;
            int ine = -1, oute = -1;
            for (int c = 0; c < clen; c++) {
                const int v = s_cyc[c];
                const float sv = S[v * NLEN + node];
                if (sv > inw) { inw = sv; ine = v; }
                const float so = cw + S[node * NLEN + v] - S[s_par[v] * NLEN + v];
                if (so > outw) { outw = so; oute = v; }
            }
            S[rep * NLEN + node] = inw;
            OI[rep * NLEN + node] = OI[ine * NLEN + node];
            OO[rep * NLEN + node] = OO[ine * NLEN + node];
            S[node * NLEN + rep] = outw;
            OO[node * NLEN + rep] = OO[node * NLEN + oute];
            OI[node * NLEN + rep] = OI[node * NLEN + oute];
        }
        __syncthreads();

        const int d = s_depth;
        g_stk_par[((size_t)b * MAXF + d) * NLEN + tid] = (unsigned char)s_par[tid];
        if (tid < clen) g_stk_cyc[((size_t)b * MAXF + d) * NLEN + tid] = (unsigned char)s_cyc[tid];
        __syncthreads();
        if (tid == 0) {
            g_stk_clen[b * MAXF + d] = clen;
            for (int c = 0; c < clen; c++) {
                const int v = s_cyc[c];
                const unsigned long long a0 = s_repA[v], a1 = s_repB[v];
                const size_t ci = (((size_t)b * MAXF + d) * NLEN + c) * 2;
                g_stk_cons[ci] = a0;
                g_stk_cons[ci + 1] = a1;
                if (c > 0) {
                    s_cur[v] = 0;
                    s_repA[rep] |= a0;
                    s_repB[rep] |= a1;
                }
            }
            s_depth = d + 1;
        }
        __syncthreads();
    }

    if (tid == 0) {
        s_final[0] = -1;
        for (int node = 1; node < NLEN; node++) {
            if (!s_cur[node]) continue;
            const int p = s_par[node];
            const int parent = OI[p * NLEN + node];
            const int child = OO[p * NLEN + node];
            s_final[child] = parent;
        }
        for (int d = s_depth - 1; d >= 0; d--) {
            const int clen = g_stk_clen[b * MAXF + d];
            const unsigned char* par = &g_stk_par[((size_t)b * MAXF + d) * NLEN];
            const unsigned char* cyc = &g_stk_cyc[((size_t)b * MAXF + d) * NLEN];
            unsigned long long f0 = 0, f1 = 0;
            for (int x = 0; x < NLEN; x++)
                if (s_final[x] != -2) {
                    if (x < 64) f0 |= 1ull << x; else f1 |= 1ull << (x - 64);
                }
            int key = -1;
            for (int c = 0; c < clen; c++) {
                const size_t ci = (((size_t)b * MAXF + d) * NLEN + c) * 2;
                if ((g_stk_cons[ci] & f0) | (g_stk_cons[ci + 1] & f1)) { key = cyc[c]; break; }
            }
            if (key < 0) continue;
            int prev = par[key];
            while (prev != key) {
                const int pp = par[prev];
                const int child = OO[pp * NLEN + prev];
                const int parent = OI[pp * NLEN + prev];
                s_final[child] = parent;
                prev = pp;
            }
        }
    }
    __syncthreads();

    if (has_tail) {
        float hv = 0.f, tv = 1.f;
        const int fe = s_final[tid];
        if (fe != -2) {
            hv = (float)fe;
            const int row = (fe < 0) ? (NLEN - 1) : fe;
            tv = (float)g_labelid[(size_t)b * TT + row * NLEN + tid];
        }
        out[(size_t)EN_ELEMS + b * NLEN + tid] = hv;
        out[(size_t)EN_ELEMS + B_ * NLEN + b * NLEN + tid] = tv;
    }
}

// ---------------------------------------------------------------------------
// Launch
// ---------------------------------------------------------------------------
extern "C" void kernel_launch(void* const* d_in, const int* in_sizes, int n_in,
                              void* d_out, int out_size)
{
    const float* X    = (const float*)d_in[0];
    const float* Wha  = (const float*)d_in[1];
    const float* bha  = (const float*)d_in[2];
    const float* Wda  = (const float*)d_in[3];
    const float* bda  = (const float*)d_in[4];
    const float* Uarc = (const float*)d_in[5];
    const float* Whl  = (const float*)d_in[6];
    const float* bhl  = (const float*)d_in[7];
    const float* Wdl  = (const float*)d_in[8];
    const float* bdl  = (const float*)d_in[9];
    const float* Ulab = (const float*)d_in[10];
    float* out = (float*)d_out;

    void* p;
    cudaGetSymbolAddress(&p, g_Wp);   float* Wp   = (float*)p;
    cudaGetSymbolAddress(&p, g_bp);   float* bp   = (float*)p;
    cudaGetSymbolAddress(&p, g_proj); float* proj = (float*)p;
    cudaGetSymbolAddress(&p, g_marc); float* marc = (float*)p;

    static int smem_set = 0;
    if (!smem_set) {
        cudaFuncSetAttribute(k_lab_fused, cudaFuncAttributeMaxDynamicSharedMemorySize, 81920);
        smem_set = 1;
    }

    const int has_tail = (out_size >= EN_ELEMS + 2 * B_ * T_);

    // pack weights + biases
    k_pack<<<(D_ * NP + 255) / 256, 256>>>(Wha, Wda, Whl, Wdl, bha, bda, bhl, bdl);

    // fused projections: proj = elu(X @ Wp + bp)   [4096 x 1280]
    k_gemm_nn<<<dim3(NP / 128, BT / 128), 256>>>(X, D_, Wp, bp, proj, D_, NP, 1);

    // marc = harc @ U_arc    [4096 x 512]
    k_gemm_nn<<<dim3(A_ / 128, BT / 128), 256>>>(proj + OFF_HARC, NP, Uarc,
                                                 (const float*)0, marc, A_, A_, 0);

    // arc_scores[b] = marc[b] @ darc[b]^T  (64x64 tiles)
    k_arc64<<<dim3(2, 2, B_), 256>>>();

    // fused label path: labsc[b,l] = (hlab[b] @ Ulab[l]) @ dlab[b]^T
    k_lab_fused<<<B_ * L_, 256, 81920>>>(Ulab);

    // softmaxes + energy + score/label matrices
    k_norm_arc<<<B_, T_>>>();
    k_energy<<<B_ * T_, T_>>>(out);

    // MST decode -> heads/tags tail
    k_mst<<<B_, NLEN>>>(out, has_tail);
}

// round 3
// speedup vs baseline: 1.2357x; 1.0027x over previous
#include <cuda_runtime.h>
#include <cuda_bf16.h>
#include <math.h>
#include <stdint.h>

// Problem constants
#define B_   32
#define T_   128
#define D_   768
#define A_   512
#define R_   128
#define L_   50
#define NP   1280               // packed projection width: 512+512+128+128
#define BT   (B_ * T_)          // 4096
#define TT   (T_ * T_)          // 16384
#define EN_ELEMS (B_ * L_ * TT) // 26,214,400
#define NLEN 128
#define MAXF 128

// ---------------------------------------------------------------------------
// Scratch (device globals; allocation is forbidden)
// ---------------------------------------------------------------------------
__device__ float g_Wp[D_ * NP];     // packed projection weights
__device__ float g_bp[NP];          // packed bias
__device__ float g_proj[BT * NP];   // packed elu(X@W+b): [harc|darc|hlab|dlab]
__device__ float g_marc[BT * A_];
__device__ float g_labsc[EN_ELEMS]; // (b,l,i,j)
__device__ float g_arc[B_ * TT];
__device__ float g_narc[B_ * TT];
__device__ float g_score[B_ * TT];  // mutated in-place by MST
__device__ int   g_labelid[B_ * TT];
__device__ unsigned char g_oldin[B_ * TT];
__device__ unsigned char g_oldout[B_ * TT];
__device__ unsigned char g_stk_par[B_ * MAXF * NLEN];
__device__ unsigned char g_stk_cyc[B_ * MAXF * NLEN];
__device__ int g_stk_clen[B_ * MAXF];
__device__ unsigned long long g_stk_cons[B_ * MAXF * NLEN * 2];

// column offsets inside packed proj
#define OFF_HARC 0
#define OFF_DARC 512
#define OFF_HLAB 1024
#define OFF_DLAB 1152

// ---------------------------------------------------------------------------
// Weight/bias packing
// ---------------------------------------------------------------------------
__global__ void k_pack(const float* __restrict__ Wha, const float* __restrict__ Wda,
                       const float* __restrict__ Whl, const float* __restrict__ Wdl,
                       const float* __restrict__ bha, const float* __restrict__ bda,
                       const float* __restrict__ bhl, const float* __restrict__ bdl)
{
    const int idx = blockIdx.x * 256 + threadIdx.x;
    if (idx < D_ * NP) {
        const int k = idx / NP;
        const int n = idx - k * NP;
        float v;
        if (n < 512)       v = Wha[k * 512 + n];
        else if (n < 1024) v = Wda[k * 512 + (n - 512)];
        else if (n < 1152) v = Whl[k * 128 + (n - 1024)];
        else               v = Wdl[k * 128 + (n - 1152)];
        g_Wp[idx] = v;
    }
    if (idx < NP) {
        float v;
        if (idx < 512)       v = bha[idx];
        else if (idx < 1024) v = bda[idx - 512];
        else if (idx < 1152) v = bhl[idx - 1024];
        else                 v = bdl[idx - 1152];
        g_bp[idx] = v;
    }
}

// ---------------------------------------------------------------------------
// Tiled 128x128 GEMM block (256 threads, 8x8 microtile, K chunk 16)
// ---------------------------------------------------------------------------
__device__ __forceinline__ void gemm_tile(
    const float* __restrict__ Ag, int lda,
    const float* __restrict__ Bg, int ldb, int transB,
    float* __restrict__ Cg, int ldc,
    int K, const float* __restrict__ biasg, int use_elu)
{
    __shared__ float As[16][128];
    __shared__ float Bs[16][128];
    const int tid = threadIdx.x;
    const int tx = tid & 15;
    const int ty = tid >> 4;
    float acc[8][8];
#pragma unroll
    for (int i = 0; i < 8; i++)
#pragma unroll
        for (int j = 0; j < 8; j++) acc[i][j] = 0.f;

    const int ra = tid >> 2;
    const int ca = (tid & 3) << 2;
    const int rb = tid >> 5;
    const int cb = (tid & 31) << 2;

    for (int kc = 0; kc < K; kc += 16) {
        float4 a0 = *(const float4*)(Ag + (size_t)ra * lda + kc + ca);
        float4 a1 = *(const float4*)(Ag + (size_t)(ra + 64) * lda + kc + ca);
        As[ca + 0][ra] = a0.x; As[ca + 1][ra] = a0.y; As[ca + 2][ra] = a0.z; As[ca + 3][ra] = a0.w;
        As[ca + 0][ra + 64] = a1.x; As[ca + 1][ra + 64] = a1.y; As[ca + 2][ra + 64] = a1.z; As[ca + 3][ra + 64] = a1.w;
        if (!transB) {
            float4 b0 = *(const float4*)(Bg + (size_t)(kc + rb) * ldb + cb);
            float4 b1 = *(const float4*)(Bg + (size_t)(kc + rb + 8) * ldb + cb);
            *(float4*)&Bs[rb][cb] = b0;
            *(float4*)&Bs[rb + 8][cb] = b1;
        } else {
            float4 b0 = *(const float4*)(Bg + (size_t)ra * ldb + kc + ca);
            float4 b1 = *(const float4*)(Bg + (size_t)(ra + 64) * ldb + kc + ca);
            Bs[ca + 0][ra] = b0.x; Bs[ca + 1][ra] = b0.y; Bs[ca + 2][ra] = b0.z; Bs[ca + 3][ra] = b0.w;
            Bs[ca + 0][ra + 64] = b1.x; Bs[ca + 1][ra + 64] = b1.y; Bs[ca + 2][ra + 64] = b1.z; Bs[ca + 3][ra + 64] = b1.w;
        }
        __syncthreads();
#pragma unroll
        for (int k = 0; k < 16; k++) {
            float af[8], bf[8];
            *(float4*)(af)     = *(const float4*)&As[k][ty * 8];
            *(float4*)(af + 4) = *(const float4*)&As[k][ty * 8 + 4];
            *(float4*)(bf)     = *(const float4*)&Bs[k][tx * 8];
            *(float4*)(bf + 4) = *(const float4*)&Bs[k][tx * 8 + 4];
#pragma unroll
            for (int i = 0; i < 8; i++)
#pragma unroll
                for (int j = 0; j < 8; j++) acc[i][j] = fmaf(af[i], bf[j], acc[i][j]);
        }
        __syncthreads();
    }
#pragma unroll
    for (int i = 0; i < 8; i++) {
        const int row = ty * 8 + i;
#pragma unroll
        for (int j = 0; j < 8; j++) {
            float v = acc[i][j];
            const int col = tx * 8 + j;
            if (biasg) v += biasg[col];
            if (use_elu) v = (v > 0.f) ? v : expm1f(v);
            Cg[(size_t)row * ldc + col] = v;
        }
    }
}

// generic NN GEMM: C[M,N] = op(A[M,K](lda) @ B[K,N] + bias)
__global__ __launch_bounds__(256, 2) void k_gemm_nn(
    const float* __restrict__ A, int lda, const float* __restrict__ Bm,
    const float* __restrict__ bias, float* __restrict__ C,
    int K, int N, int use_elu)
{
    const int m0 = blockIdx.y * 128;
    const int n0 = blockIdx.x * 128;
    gemm_tile(A + (size_t)m0 * lda, lda, Bm + n0, N, 0,
              C + (size_t)m0 * N + n0, N, K,
              bias ? (bias + n0) : (const float*)0, use_elu);
}

// ---------------------------------------------------------------------------
// arc[b,i,j] = sum_a marc[b,i,a] * darc[b,j,a]  — 64x64 tiles, grid (2,2,32)
// ---------------------------------------------------------------------------
__global__ __launch_bounds__(256, 4) void k_arc64()
{
    const int b = blockIdx.z;
    const int m0 = blockIdx.y * 64;
    const int n0 = blockIdx.x * 64;
    const float* Ag = g_marc + (size_t)b * T_ * A_ + (size_t)m0 * A_;
    const float* Bg = g_proj + (size_t)b * T_ * NP + (size_t)n0 * NP + OFF_DARC;

    __shared__ float As[16][64];
    __shared__ float Bs[16][64];
    const int tid = threadIdx.x;
    const int tx = tid & 15;
    const int ty = tid >> 4;
    const int ra = tid >> 2;          // 0..63
    const int ca = (tid & 3) << 2;

    float acc[4][4];
#pragma unroll
    for (int i = 0; i < 4; i++)
#pragma unroll
        for (int j = 0; j < 4; j++) acc[i][j] = 0.f;

    for (int kc = 0; kc < A_; kc += 16) {
        float4 a0 = *(const float4*)(Ag + (size_t)ra * A_ + kc + ca);
        float4 b0 = *(const float4*)(Bg + (size_t)ra * NP + kc + ca);
        As[ca + 0][ra] = a0.x; As[ca + 1][ra] = a0.y; As[ca + 2][ra] = a0.z; As[ca + 3][ra] = a0.w;
        Bs[ca + 0][ra] = b0.x; Bs[ca + 1][ra] = b0.y; Bs[ca + 2][ra] = b0.z; Bs[ca + 3][ra] = b0.w;
        __syncthreads();
#pragma unroll
        for (int k = 0; k < 16; k++) {
            float af[4], bf[4];
            *(float4*)af = *(const float4*)&As[k][ty * 4];
            *(float4*)bf = *(const float4*)&Bs[k][tx * 4];
#pragma unroll
            for (int i = 0; i < 4; i++)
#pragma unroll
                for (int j = 0; j < 4; j++) acc[i][j] = fmaf(af[i], bf[j], acc[i][j]);
        }
        __syncthreads();
    }
    float* C = g_arc + (size_t)b * TT + (size_t)(m0 + ty * 4) * T_ + n0 + tx * 4;
#pragma unroll
    for (int i = 0; i < 4; i++)
        *(float4*)(C + (size_t)i * T_) = make_float4(acc[i][0], acc[i][1], acc[i][2], acc[i][3]);
}

// ---------------------------------------------------------------------------
// Fused label path: per (b,l): tmp = hlab[b] @ Ulab[l] (smem), labsc = tmp @ dlab[b]^T
// dynamic smem: As(16x128) + Bs(16x128) + Tmp(128x128) = 80KB
// ---------------------------------------------------------------------------
__global__ __launch_bounds__(256) void k_lab_fused(const float* __restrict__ Ulab)
{
    extern __shared__ float sm[];
    float (*As)[128] = (float (*)[128])sm;
    float (*Bs)[128] = (float (*)[128])(sm + 2048);
    float* Tmp = sm + 4096;

    const int z = blockIdx.x;
    const int b = z / L_;
    const int l = z - b * L_;
    const float* hlab = g_proj + (size_t)b * T_ * NP + OFF_HLAB;
    const float* dlab = g_proj + (size_t)b * T_ * NP + OFF_DLAB;
    const float* U = Ulab + (size_t)l * R_ * R_;

    const int tid = threadIdx.x;
    const int tx = tid & 15;
    const int ty = tid >> 4;
    const int ra = tid >> 2;
    const int ca = (tid & 3) << 2;
    const int rb = tid >> 5;
    const int cb = (tid & 31) << 2;

    float acc[8][8];
#pragma unroll
    for (int i = 0; i < 8; i++)
#pragma unroll
        for (int j = 0; j < 8; j++) acc[i][j] = 0.f;

    // phase 1: tmp = hlab @ U   (K = 128)
    for (int kc = 0; kc < R_; kc += 16) {
        float4 a0 = *(const float4*)(hlab + (size_t)ra * NP + kc + ca);
        float4 a1 = *(const float4*)(hlab + (size_t)(ra + 64) * NP + kc + ca);
        As[ca + 0][ra] = a0.x; As[ca + 1][ra] = a0.y; As[ca + 2][ra] = a0.z; As[ca + 3][ra] = a0.w;
        As[ca + 0][ra + 64] = a1.x; As[ca + 1][ra + 64] = a1.y; As[ca + 2][ra + 64] = a1.z; As[ca + 3][ra + 64] = a1.w;
        float4 b0 = *(const float4*)(U + (size_t)(kc + rb) * R_ + cb);
        float4 b1 = *(const float4*)(U + (size_t)(kc + rb + 8) * R_ + cb);
        *(float4*)&Bs[rb][cb] = b0;
        *(float4*)&Bs[rb + 8][cb] = b1;
        __syncthreads();
#pragma unroll
        for (int k = 0; k < 16; k++) {
            float af[8], bf[8];
            *(float4*)(af)     = *(const float4*)&As[k][ty * 8];
            *(float4*)(af + 4) = *(const float4*)&As[k][ty * 8 + 4];
            *(float4*)(bf)     = *(const float4*)&Bs[k][tx * 8];
            *(float4*)(bf + 4) = *(const float4*)&Bs[k][tx * 8 + 4];
#pragma unroll
            for (int i = 0; i < 8; i++)
#pragma unroll
                for (int j = 0; j < 8; j++) acc[i][j] = fmaf(af[i], bf[j], acc[i][j]);
        }
        __syncthreads();
    }
    // write tmp to smem
#pragma unroll
    for (int i = 0; i < 8; i++) {
        const int row = ty * 8 + i;
        *(float4*)&Tmp[row * 128 + tx * 8]     = make_float4(acc[i][0], acc[i][1], acc[i][2], acc[i][3]);
        *(float4*)&Tmp[row * 128 + tx * 8 + 4] = make_float4(acc[i][4], acc[i][5], acc[i][6], acc[i][7]);
    }
    __syncthreads();

    // phase 2: labsc = Tmp @ dlab^T   (K = 128)
#pragma unroll
    for (int i = 0; i < 8; i++)
#pragma unroll
        for (int j = 0; j < 8; j++) acc[i][j] = 0.f;

    for (int kc = 0; kc < R_; kc += 16) {
        float4 b0 = *(const float4*)(dlab + (size_t)ra * NP + kc + ca);
        float4 b1 = *(const float4*)(dlab + (size_t)(ra + 64) * NP + kc + ca);
        Bs[ca + 0][ra] = b0.x; Bs[ca + 1][ra] = b0.y; Bs[ca + 2][ra] = b0.z; Bs[ca + 3][ra] = b0.w;
        Bs[ca + 0][ra + 64] = b1.x; Bs[ca + 1][ra + 64] = b1.y; Bs[ca + 2][ra + 64] = b1.z; Bs[ca + 3][ra + 64] = b1.w;
        __syncthreads();
#pragma unroll
        for (int k = 0; k < 16; k++) {
            float af[8], bf[8];
#pragma unroll
            for (int i = 0; i < 8; i++) af[i] = Tmp[(ty * 8 + i) * 128 + kc + k];
            *(float4*)(bf)     = *(const float4*)&Bs[k][tx * 8];
            *(float4*)(bf + 4) = *(const float4*)&Bs[k][tx * 8 + 4];
#pragma unroll
            for (int i = 0; i < 8; i++)
#pragma unroll
                for (int j = 0; j < 8; j++) acc[i][j] = fmaf(af[i], bf[j], acc[i][j]);
        }
        __syncthreads();
    }
    float* out = g_labsc + (size_t)z * TT;
#pragma unroll
    for (int i = 0; i < 8; i++) {
        const int row = ty * 8 + i;
        *(float4*)(out + (size_t)row * T_ + tx * 8)     = make_float4(acc[i][0], acc[i][1], acc[i][2], acc[i][3]);
        *(float4*)(out + (size_t)row * T_ + tx * 8 + 4) = make_float4(acc[i][4], acc[i][5], acc[i][6], acc[i][7]);
    }
}

// norm_arc: log_softmax over heads (axis i) per (b, j)
__global__ void k_norm_arc()
{
    const int b = blockIdx.x;
    const int j = threadIdx.x;
    const float* base = g_arc + (size_t)b * TT;
    float m = -3.4e38f;
#pragma unroll 8
    for (int i = 0; i < T_; i++) m = fmaxf(m, base[i * T_ + j]);
    float s = 0.f;
#pragma unroll 8
    for (int i = 0; i < T_; i++) s += expf(base[i * T_ + j] - m);
    const float ls = logf(s);
    float* nb = g_narc + (size_t)b * TT;
#pragma unroll 8
    for (int i = 0; i < T_; i++) nb[i * T_ + j] = (base[i * T_ + j] - m) - ls;
}

// energy[b,l,i,j] = exp(narc[b,i,j] + log_softmax_l(labsc)[b,l,i,j])
__global__ void k_energy(float* __restrict__ energy)
{
    const int bi = blockIdx.x;
    const int b = bi >> 7;
    const int i = bi & 127;
    const int j = threadIdx.x;
    const size_t base = (size_t)b * (L_ * TT) + (size_t)i * T_ + j;
    float m = -3.4e38f;
#pragma unroll 5
    for (int l = 0; l < L_; l++) m = fmaxf(m, g_labsc[base + (size_t)l * TT]);
    float s = 0.f;
#pragma unroll 5
    for (int l = 0; l < L_; l++) s += expf(g_labsc[base + (size_t)l * TT] - m);
    const float ls = logf(s);
    const float na = g_narc[(size_t)b * TT + i * T_ + j];
    float best = -3.4e38f;
    int arg = 0;
#pragma unroll 5
    for (int l = 0; l < L_; l++) {
        const float x = g_labsc[base + (size_t)l * TT];
        const float e = expf(na + ((x - m) - ls));
        energy[base + (size_t)l * TT] = e;
        if (e > best) { best = e; arg = l; }
    }
    g_score[(size_t)b * TT + i * T_ + j] = (i == j) ? 0.f : best;
    g_labelid[(size_t)b * TT + i * T_ + j] = arg;
}

// ---------------------------------------------------------------------------
// Chu-Liu-Edmonds MST (one block per batch, iterative with explicit stack)
// ---------------------------------------------------------------------------
__global__ __launch_bounds__(128) void k_mst(float* __restrict__ out, int has_tail)
{
    const int b = blockIdx.x;
    const int tid = threadIdx.x;
    float* S = g_score + (size_t)b * TT;
    unsigned char* OI = g_oldin + (size_t)b * TT;
    unsigned char* OO = g_oldout + (size_t)b * TT;

    __shared__ int s_par[NLEN];
    __shared__ unsigned char s_cur[NLEN];
    __shared__ unsigned char s_incyc[NLEN];
    __shared__ unsigned char s_added[NLEN];
    __shared__ int s_cyc[NLEN];
    __shared__ int s_final[NLEN];
    __shared__ unsigned long long s_repA[NLEN], s_repB[NLEN];
    __shared__ int s_clen, s_has, s_depth;
    __shared__ float s_cw;

    for (int idx = tid; idx < TT; idx += NLEN) {
        const int i = idx >> 7, j = idx & 127;
        OI[idx] = (unsigned char)((i == j) ? 0 : i);
        OO[idx] = (unsigned char)((i == j) ? 0 : j);
    }
    s_cur[tid] = 1;
    s_repA[tid] = (tid < 64) ? (1ull << tid) : 0ull;
    s_repB[tid] = (tid >= 64) ? (1ull << (tid - 64)) : 0ull;
    s_final[tid] = -2;
    if (tid == 0) s_depth = 0;
    __syncthreads();

    while (true) {
        if (tid == 0) {
            s_par[0] = -1;
        } else {
            int par = 0;
            if (s_cur[tid]) {
                float best = S[tid];
                for (int n2 = 1; n2 < NLEN; n2++) {
                    if (n2 != tid && s_cur[n2]) {
                        const float v = S[n2 * NLEN + tid];
                        if (v > best) { best = v; par = n2; }
                    }
                }
            }
            s_par[tid] = par;
        }
        __syncthreads();

        if (tid == 0) {
            for (int i = 0; i < NLEN; i++) s_added[i] = 0;
            s_added[0] = 1;
            int has = 0, clen = 0;
            for (int i = 1; i < NLEN; i++) {
                if (s_added[i] || !s_cur[i]) continue;
                unsigned long long t0 = 0, t1 = 0;
                if (i < 64) t0 |= 1ull << i; else t1 |= 1ull << (i - 64);
                s_added[i] = 1;
                has = 1;
                int next = i;
                while (true) {
                    const int p = s_par[next];
                    const int inc = (p < 64) ? (int)((t0 >> p) & 1ull)
                                             : (int)((t1 >> (p - 64)) & 1ull);
                    if (inc) break;
                    next = p;
                    if (s_added[next]) { has = 0; break; }
                    s_added[next] = 1;
                    if (next < 64) t0 |= 1ull << next; else t1 |= 1ull << (next - 64);
                }
                if (has) {
                    clen = 0;
                    s_cyc[clen++] = next;
                    int n2 = s_par[next];
                    while (n2 != next) { s_cyc[clen++] = n2; n2 = s_par[n2]; }
                    break;
                }
            }
            s_has = has; s_clen = clen;
            if (has) {
                float cw = 0.f;
                for (int c = 0; c < clen; c++) {
                    const int v = s_cyc[c];
                    cw += S[s_par[v] * NLEN + v];
                }
                s_cw = cw;
            }
        }
        __syncthreads();
        if (!s_has) break;

        const int clen = s_clen;
        const int rep = s_cyc[0];
        const float cw = s_cw;
        s_incyc[tid] = 0;
        __syncthreads();
        if (tid < clen) s_incyc[s_cyc[tid]] = 1;
        __syncthreads();

        if (s_cur[tid] && !s_incyc[tid]) {
            const int node = tid;
            float inw = -3.4e38f, outw = -3.4e38f;
            int ine = -1, oute = -1;
            for (int c = 0; c < clen; c++) {
                const int v = s_cyc[c];
                const float sv = S[v * NLEN + node];
                if (sv > inw) { inw = sv; ine = v; }
                const float so = cw + S[node * NLEN + v] - S[s_par[v] * NLEN + v];
                if (so > outw) { outw = so; oute = v; }
            }
            S[rep * NLEN + node] = inw;
            OI[rep * NLEN + node] = OI[ine * NLEN + node];
            OO[rep * NLEN + node] = OO[ine * NLEN + node];
            S[node * NLEN + rep] = outw;
            OO[node * NLEN + rep] = OO[node * NLEN + oute];
            OI[node * NLEN + rep] = OI[node * NLEN + oute];
        }
        __syncthreads();

        const int d = s_depth;
        g_stk_par[((size_t)b * MAXF + d) * NLEN + tid] = (unsigned char)s_par[tid];
        if (tid < clen) g_stk_cyc[((size_t)b * MAXF + d) * NLEN + tid] = (unsigned char)s_cyc[tid];
        __syncthreads();
        if (tid == 0) {
            g_stk_clen[b * MAXF + d] = clen;
            for (int c = 0; c < clen; c++) {
                const int v = s_cyc[c];
                const unsigned long long a0 = s_repA[v], a1 = s_repB[v];
                const size_t ci = (((size_t)b * MAXF + d) * NLEN + c) * 2;
                g_stk_cons[ci] = a0;
                g_stk_cons[ci + 1] = a1;
                if (c > 0) {
                    s_cur[v] = 0;
                    s_repA[rep] |= a0;
                    s_repB[rep] |= a1;
                }
            }
            s_depth = d + 1;
        }
        __syncthreads();
    }

    if (tid == 0) {
        s_final[0] = -1;
        for (int node = 1; node < NLEN; node++) {
            if (!s_cur[node]) continue;
            const int p = s_par[node];
            const int parent = OI[p * NLEN + node];
            const int child = OO[p * NLEN + node];
            s_final[child] = parent;
        }
        for (int d = s_depth - 1; d >= 0; d--) {
            const int clen = g_stk_clen[b * MAXF + d];
            const unsigned char* par = &g_stk_par[((size_t)b * MAXF + d) * NLEN];
            const unsigned char* cyc = &g_stk_cyc[((size_t)b * MAXF + d) * NLEN];
            unsigned long long f0 = 0, f1 = 0;
            for (int x = 0; x < NLEN; x++)
                if (s_final[x] != -2) {
                    if (x < 64) f0 |= 1ull << x; else f1 |= 1ull << (x - 64);
                }
            int key = -1;
            for (int c = 0; c < clen; c++) {
                const size_t ci = (((size_t)b * MAXF + d) * NLEN + c) * 2;
                if ((g_stk_cons[ci] & f0) | (g_stk_cons[ci + 1] & f1)) { key = cyc[c]; break; }
            }
            if (key < 0) continue;
            int prev = par[key];
            while (prev != key) {
                const int pp = par[prev];
                const int child = OO[pp * NLEN + prev];
                const int parent = OI[pp * NLEN + prev];
                s_final[child] = parent;
                prev = pp;
            }
        }
    }
    __syncthreads();

    if (has_tail) {
        float hv = 0.f, tv = 1.f;
        const int fe = s_final[tid];
        if (fe != -2) {
            hv = (float)fe;
            const int row = (fe < 0) ? (NLEN - 1) : fe;
            tv = (float)g_labelid[(size_t)b * TT + row * NLEN + tid];
        }
        out[(size_t)EN_ELEMS + b * NLEN + tid] = hv;
        out[(size_t)EN_ELEMS + B_ * NLEN + b * NLEN + tid] = tv;
    }
}

// ---------------------------------------------------------------------------
// Launch
// ---------------------------------------------------------------------------
extern "C" void kernel_launch(void* const* d_in, const int* in_sizes, int n_in,
                              void* d_out, int out_size)
{
    const float* X    = (const float*)d_in[0];
    const float* Wha  = (const float*)d_in[1];
    const float* bha  = (const float*)d_in[2];
    const float* Wda  = (const float*)d_in[3];
    const float* bda  = (const float*)d_in[4];
    const float* Uarc = (const float*)d_in[5];
    const float* Whl  = (const float*)d_in[6];
    const float* bhl  = (const float*)d_in[7];
    const float* Wdl  = (const float*)d_in[8];
    const float* bdl  = (const float*)d_in[9];
    const float* Ulab = (const float*)d_in[10];
    float* out = (float*)d_out;

    void* p;
    cudaGetSymbolAddress(&p, g_Wp);   float* Wp   = (float*)p;
    cudaGetSymbolAddress(&p, g_bp);   float* bp   = (float*)p;
    cudaGetSymbolAddress(&p, g_proj); float* proj = (float*)p;
    cudaGetSymbolAddress(&p, g_marc); float* marc = (float*)p;

    static int smem_set = 0;
    if (!smem_set) {
        cudaFuncSetAttribute(k_lab_fused, cudaFuncAttributeMaxDynamicSharedMemorySize, 81920);
        smem_set = 1;
    }

    const int has_tail = (out_size >= EN_ELEMS + 2 * B_ * T_);

    // pack weights + biases
    k_pack<<<(D_ * NP + 255) / 256, 256>>>(Wha, Wda, Whl, Wdl, bha, bda, bhl, bdl);

    // fused projections: proj = elu(X @ Wp + bp)   [4096 x 1280]
    k_gemm_nn<<<dim3(NP / 128, BT / 128), 256>>>(X, D_, Wp, bp, proj, D_, NP, 1);

    // marc = harc @ U_arc    [4096 x 512]
    k_gemm_nn<<<dim3(A_ / 128, BT / 128), 256>>>(proj + OFF_HARC, NP, Uarc,
                                                 (const float*)0, marc, A_, A_, 0);

    // arc_scores[b] = marc[b] @ darc[b]^T  (64x64 tiles)
    k_arc64<<<dim3(2, 2, B_), 256>>>();

    // fused label path: labsc[b,l] = (hlab[b] @ Ulab[l]) @ dlab[b]^T
    k_lab_fused<<<B_ * L_, 256, 81920>>>(Ulab);

    // softmaxes + energy + score/label matrices
    k_norm_arc<<<B_, T_>>>();
    k_energy<<<B_ * T_, T_>>>(out);

    // MST decode -> heads/tags tail
    k_mst<<<B_, NLEN>>>(out, has_tail);
}

// round 5
// speedup vs baseline: 1.3753x; 1.1130x over previous
#include <cuda_runtime.h>
#include <math.h>
#include <stdint.h>

#define B_   32
#define T_   128
#define D_   768
#define A_   512
#define R_   128
#define L_   50
#define NP   1280
#define BT   (B_ * T_)
#define TT   (T_ * T_)
#define EN_ELEMS (B_ * L_ * TT)
#define NLEN 128
#define MAXF 128
#define OFF_HARC 0
#define OFF_DARC 512
#define OFF_HLAB 1024
#define OFF_DLAB 1152

// ---------------------------------------------------------------------------
// Scratch (device globals; allocation is forbidden)
// ---------------------------------------------------------------------------
__device__ float g_Wt[NP * D_];          // packed projection weights, [n][k]
__device__ float g_bp[NP];
__device__ float g_Uat[A_ * A_];         // Uarc^T  [n][k]
__device__ float g_Ult[L_ * R_ * R_];    // Ulab^T per l: [s][r]
__device__ float g_proj[BT * NP];        // elu(X@W+b): [harc|darc|hlab|dlab]
__device__ float g_marc[BT * A_];
__device__ float g_hl[EN_ELEMS];         // hlab @ Ulab per (b,l)
__device__ float g_arc[B_ * TT];
__device__ float g_narc[B_ * TT];
__device__ float g_score[B_ * TT];
__device__ int   g_labelid[B_ * TT];
__device__ unsigned char g_oldin[B_ * TT];
__device__ unsigned char g_oldout[B_ * TT];
__device__ unsigned char g_stk_par[B_ * MAXF * NLEN];
__device__ unsigned char g_stk_cyc[B_ * MAXF * NLEN];
__device__ int g_stk_clen[B_ * MAXF];
__device__ unsigned long long g_stk_cons[B_ * MAXF * NLEN * 2];

// ---------------------------------------------------------------------------
// helpers
// ---------------------------------------------------------------------------
__device__ __forceinline__ uint32_t f2tf32(float v) {
    uint32_t r;
    asm("cvt.rna.tf32.f32 %0, %1;" : "=r"(r) : "f"(v));
    return r;
}
__device__ __forceinline__ void mma8(float* d, const uint32_t* a, const uint32_t* b) {
    asm volatile(
        "mma.sync.aligned.m16n8k8.row.col.f32.tf32.tf32.f32 "
        "{%0,%1,%2,%3}, {%4,%5,%6,%7}, {%8,%9}, {%0,%1,%2,%3};"
        : "+f"(d[0]), "+f"(d[1]), "+f"(d[2]), "+f"(d[3])
        : "r"(a[0]), "r"(a[1]), "r"(a[2]), "r"(a[3]), "r"(b[0]), "r"(b[1]));
}

// ---------------------------------------------------------------------------
// input prep: transposed packs (plain fp32; limb split happens at SMEM fill)
// ---------------------------------------------------------------------------
__global__ void k_prep_W(const float* __restrict__ Wha, const float* __restrict__ Wda,
                         const float* __restrict__ Whl, const float* __restrict__ Wdl,
                         const float* __restrict__ bha, const float* __restrict__ bda,
                         const float* __restrict__ bhl, const float* __restrict__ bdl)
{
    const int idx = blockIdx.x * 256 + threadIdx.x;
    if (idx < NP * D_) {
        const int n = idx / D_, k = idx - n * D_;
        float v;
        if (n < 512)       v = Wha[k * 512 + n];
        else if (n < 1024) v = Wda[k * 512 + (n - 512)];
        else if (n < 1152) v = Whl[k * 128 + (n - 1024)];
        else               v = Wdl[k * 128 + (n - 1152)];
        g_Wt[idx] = v;
    }
    if (idx < NP) {
        float v;
        if (idx < 512)       v = bha[idx];
        else if (idx < 1024) v = bda[idx - 512];
        else if (idx < 1152) v = bhl[idx - 1024];
        else                 v = bdl[idx - 1152];
        g_bp[idx] = v;
    }
}
__global__ void k_prep_Ua(const float* __restrict__ U) {
    const int idx = blockIdx.x * 256 + threadIdx.x;
    if (idx < A_ * A_) {
        const int n = idx / A_, k = idx - n * A_;
        g_Uat[idx] = U[k * A_ + n];
    }
}
__global__ void k_prep_Ul(const float* __restrict__ U) {
    const int idx = blockIdx.x * 256 + threadIdx.x;
    if (idx < L_ * R_ * R_) {
        const int l = idx / (R_ * R_);
        const int rem = idx - l * (R_ * R_);
        const int s = rem >> 7, r = rem & 127;
        g_Ult[idx] = U[l * R_ * R_ + r * R_ + s];
    }
}

// ---------------------------------------------------------------------------
// Generic tf32x3 warp-MMA GEMM: C[128,128] tile = A[M,K] @ B[N,K]^T
// 256 threads, 8 warps (2x4), warp tile 64x32, Kc=32, padded stride 36.
// mode 0: plain fp32 store; mode 1: bias + ELU.
// zmode 0: zA=zB=z ; 1: zA=z/L, zB=z%L ; 2: zA=z, zB=z/L
// ---------------------------------------------------------------------------
#define SPAD 36
#define SMEMSZ (4 * 128 * SPAD * 4)

__global__ __launch_bounds__(256) void k_mma(
    const float* __restrict__ A, long long sA, int lda,
    const float* __restrict__ B, long long sB, int ldb,
    float* __restrict__ C, long long sC, int ldc,
    const float* __restrict__ bias, int K, int mode, int zmode)
{
    extern __shared__ float sm[];
    float* SAh = sm;
    float* SAl = sm + 128 * SPAD;
    float* SBh = sm + 2 * 128 * SPAD;
    float* SBl = sm + 3 * 128 * SPAD;

    const int tid = threadIdx.x;
    const int lane = tid & 31;
    const int wid = tid >> 5;
    const int wr = wid >> 2;       // 0..1
    const int wc = wid & 3;        // 0..3
    const int g = lane >> 2, t = lane & 3;

    const int z = blockIdx.z;
    int zA = z, zB = z;
    if (zmode == 1) { zA = z / L_; zB = z - zA * L_; }
    else if (zmode == 2) { zB = z / L_; }
    const int m0 = blockIdx.y * 128, n0 = blockIdx.x * 128;
    A += (size_t)zA * sA + (size_t)m0 * lda;
    B += (size_t)zB * sB + (size_t)n0 * ldb;

    float acc[4][4][4];
#pragma unroll
    for (int i = 0; i < 4; i++)
#pragma unroll
        for (int j = 0; j < 4; j++)
#pragma unroll
            for (int q = 0; q < 4; q++) acc[i][j][q] = 0.f;

    const int frow = tid >> 1;
    const int fk = (tid & 1) << 4;

    for (int kc = 0; kc < K; kc += 32) {
        // ---- fill + limb split ----
        {
            const float* pa = A + (size_t)frow * lda + kc + fk;
            const float* pb = B + (size_t)frow * ldb + kc + fk;
            const int so = frow * SPAD + fk;
#pragma unroll
            for (int q = 0; q < 16; q += 4) {
                float4 va = *(const float4*)(pa + q);
                float4 vb = *(const float4*)(pb + q);
                float4 vah, val, vbh, vbl;
#pragma unroll
                for (int c = 0; c < 4; c++) {
                    float x = ((const float*)&va)[c];
                    float h = __uint_as_float(f2tf32(x));
                    ((float*)&vah)[c] = h;
                    ((float*)&val)[c] = __uint_as_float(f2tf32(x - h));
                    x = ((const float*)&vb)[c];
                    h = __uint_as_float(f2tf32(x));
                    ((float*)&vbh)[c] = h;
                    ((float*)&vbl)[c] = __uint_as_float(f2tf32(x - h));
                }
                *(float4*)(SAh + so + q) = vah;
                *(float4*)(SAl + so + q) = val;
                *(float4*)(SBh + so + q) = vbh;
                *(float4*)(SBl + so + q) = vbl;
            }
        }
        __syncthreads();

        // ---- compute: 4 k-steps of 8 ----
#pragma unroll
        for (int ks = 0; ks < 4; ks++) {
            const int kb = ks * 8;
            uint32_t Ah[4][4], Bh[4][2];
#pragma unroll
            for (int mt = 0; mt < 4; mt++) {
                const int rA = (wr * 64 + mt * 16 + g) * SPAD + kb + t;
                Ah[mt][0] = __float_as_uint(SAh[rA]);
                Ah[mt][1] = __float_as_uint(SAh[rA + 8 * SPAD]);
                Ah[mt][2] = __float_as_uint(SAh[rA + 4]);
                Ah[mt][3] = __float_as_uint(SAh[rA + 8 * SPAD + 4]);
            }
#pragma unroll
            for (int nt = 0; nt < 4; nt++) {
                const int cB = (wc * 32 + nt * 8 + g) * SPAD + kb + t;
                Bh[nt][0] = __float_as_uint(SBh[cB]);
                Bh[nt][1] = __float_as_uint(SBh[cB + 4]);
            }
            // hh
#pragma unroll
            for (int mt = 0; mt < 4; mt++)
#pragma unroll
                for (int nt = 0; nt < 4; nt++) mma8(acc[mt][nt], Ah[mt], Bh[nt]);
            // hl: Ah x Bl
            {
                uint32_t Bl[4][2];
#pragma unroll
                for (int nt = 0; nt < 4; nt++) {
                    const int cB = (wc * 32 + nt * 8 + g) * SPAD + kb + t;
                    Bl[nt][0] = __float_as_uint(SBl[cB]);
                    Bl[nt][1] = __float_as_uint(SBl[cB + 4]);
                }
#pragma unroll
                for (int mt = 0; mt < 4; mt++)
#pragma unroll
                    for (int nt = 0; nt < 4; nt++) mma8(acc[mt][nt], Ah[mt], Bl[nt]);
            }
            // lh: Al x Bh
            {
                uint32_t Al[4][4];
#pragma unroll
                for (int mt = 0; mt < 4; mt++) {
                    const int rA = (wr * 64 + mt * 16 + g) * SPAD + kb + t;
                    Al[mt][0] = __float_as_uint(SAl[rA]);
                    Al[mt][1] = __float_as_uint(SAl[rA + 8 * SPAD]);
                    Al[mt][2] = __float_as_uint(SAl[rA + 4]);
                    Al[mt][3] = __float_as_uint(SAl[rA + 8 * SPAD + 4]);
                }
#pragma unroll
                for (int mt = 0; mt < 4; mt++)
#pragma unroll
                    for (int nt = 0; nt < 4; nt++) mma8(acc[mt][nt], Al[mt], Bh[nt]);
            }
        }
        __syncthreads();
    }

    // ---- epilogue ----
    C += (size_t)z * sC;
#pragma unroll
    for (int mt = 0; mt < 4; mt++) {
        const int row = m0 + wr * 64 + mt * 16 + g;
#pragma unroll
        for (int nt = 0; nt < 4; nt++) {
            const int col = n0 + wc * 32 + nt * 8 + 2 * t;
            float v0 = acc[mt][nt][0], v1 = acc[mt][nt][1];
            float v2 = acc[mt][nt][2], v3 = acc[mt][nt][3];
            if (mode == 1) {
                const float b0 = bias[col], b1 = bias[col + 1];
                v0 += b0; v1 += b1; v2 += b0; v3 += b1;
                v0 = (v0 > 0.f) ? v0 : expm1f(v0);
                v1 = (v1 > 0.f) ? v1 : expm1f(v1);
                v2 = (v2 > 0.f) ? v2 : expm1f(v2);
                v3 = (v3 > 0.f) ? v3 : expm1f(v3);
            }
            *(float2*)(C + (size_t)row * ldc + col) = make_float2(v0, v1);
            *(float2*)(C + (size_t)(row + 8) * ldc + col) = make_float2(v2, v3);
        }
    }
}

// ---------------------------------------------------------------------------
// softmaxes / energy
// ---------------------------------------------------------------------------
__global__ void k_norm_arc()
{
    const int b = blockIdx.x, j = threadIdx.x;
    const float* base = g_arc + (size_t)b * TT;
    float m = -3.4e38f;
#pragma unroll 8
    for (int i = 0; i < T_; i++) m = fmaxf(m, base[i * T_ + j]);
    float s = 0.f;
#pragma unroll 8
    for (int i = 0; i < T_; i++) s += expf(base[i * T_ + j] - m);
    const float ls = logf(s);
    float* nb = g_narc + (size_t)b * TT;
#pragma unroll 8
    for (int i = 0; i < T_; i++) nb[i * T_ + j] = (base[i * T_ + j] - m) - ls;
}

// energy in-place over labsc (stored in `out`): reads all 50 first, then writes.
__global__ void k_energy(float* __restrict__ energy)
{
    const int bi = blockIdx.x, b = bi >> 7, i = bi & 127, j = threadIdx.x;
    const size_t base = (size_t)b * (L_ * TT) + (size_t)i * T_ + j;
    float x[L_];
#pragma unroll
    for (int l = 0; l < L_; l++) x[l] = energy[base + (size_t)l * TT];
    float m = -3.4e38f;
#pragma unroll
    for (int l = 0; l < L_; l++) m = fmaxf(m, x[l]);
    float s = 0.f;
#pragma unroll
    for (int l = 0; l < L_; l++) s += expf(x[l] - m);
    const float ls = logf(s);
    const float na = g_narc[(size_t)b * TT + i * T_ + j];
    float best = -3.4e38f;
    int arg = 0;
#pragma unroll
    for (int l = 0; l < L_; l++) {
        const float e = expf(na + ((x[l] - m) - ls));
        energy[base + (size_t)l * TT] = e;
        if (e > best) { best = e; arg = l; }
    }
    g_score[(size_t)b * TT + i * T_ + j] = (i == j) ? 0.f : best;
    g_labelid[(size_t)b * TT + i * T_ + j] = arg;
}

// ---------------------------------------------------------------------------
// Chu-Liu-Edmonds MST (one block per batch, iterative with explicit stack)
// ---------------------------------------------------------------------------
__global__ __launch_bounds__(128) void k_mst(float* __restrict__ out, int has_tail)
{
    const int b = blockIdx.x, tid = threadIdx.x;
    float* S = g_score + (size_t)b * TT;
    unsigned char* OI = g_oldin + (size_t)b * TT;
    unsigned char* OO = g_oldout + (size_t)b * TT;
    __shared__ int s_par[NLEN];
    __shared__ unsigned char s_cur[NLEN], s_incyc[NLEN], s_added[NLEN];
    __shared__ int s_cyc[NLEN], s_final[NLEN];
    __shared__ unsigned long long s_repA[NLEN], s_repB[NLEN];
    __shared__ int s_clen, s_has, s_depth;
    __shared__ float s_cw;

    for (int idx = tid; idx < TT; idx += NLEN) {
        const int i = idx >> 7, j = idx & 127;
        OI[idx] = (unsigned char)((i == j) ? 0 : i);
        OO[idx] = (unsigned char)((i == j) ? 0 : j);
    }
    s_cur[tid] = 1;
    s_repA[tid] = (tid < 64) ? (1ull << tid) : 0ull;
    s_repB[tid] = (tid >= 64) ? (1ull << (tid - 64)) : 0ull;
    s_final[tid] = -2;
    if (tid == 0) s_depth = 0;
    __syncthreads();

    while (true) {
        if (tid == 0) s_par[0] = -1;
        else {
            int par = 0;
            if (s_cur[tid]) {
                float best = S[tid];
                for (int n2 = 1; n2 < NLEN; n2++)
                    if (n2 != tid && s_cur[n2]) {
                        const float v = S[n2 * NLEN + tid];
                        if (v > best) { best = v; par = n2; }
                    }
            }
            s_par[tid] = par;
        }
        __syncthreads();

        if (tid == 0) {
            for (int i = 0; i < NLEN; i++) s_added[i] = 0;
            s_added[0] = 1;
            int has = 0, clen = 0;
            for (int i = 1; i < NLEN; i++) {
                if (s_added[i] || !s_cur[i]) continue;
                unsigned long long t0 = 0, t1 = 0;
                if (i < 64) t0 |= 1ull << i; else t1 |= 1ull << (i - 64);
                s_added[i] = 1;
                has = 1;
                int next = i;
                while (true) {
                    const int p = s_par[next];
                    const int inc = (p < 64) ? (int)((t0 >> p) & 1ull) : (int)((t1 >> (p - 64)) & 1ull);
                    if (inc) break;
                    next = p;
                    if (s_added[next]) { has = 0; break; }
                    s_added[next] = 1;
                    if (next < 64) t0 |= 1ull << next; else t1 |= 1ull << (next - 64);
                }
                if (has) {
                    clen = 0;
                    s_cyc[clen++] = next;
                    int n2 = s_par[next];
                    while (n2 != next) { s_cyc[clen++] = n2; n2 = s_par[n2]; }
                    break;
                }
            }
            s_has = has; s_clen = clen;
            if (has) {
                float cw = 0.f;
                for (int c = 0; c < clen; c++) { const int v = s_cyc[c]; cw += S[s_par[v] * NLEN + v]; }
                s_cw = cw;
            }
        }
        __syncthreads();
        if (!s_has) break;

        const int clen = s_clen;
        const int rep = s_cyc[0];
        const float cw = s_cw;
        s_incyc[tid] = 0;
        __syncthreads();
        if (tid < clen) s_incyc[s_cyc[tid]] = 1;
        __syncthreads();

        if (s_cur[tid] && !s_incyc[tid]) {
            const int node = tid;
            float inw = -3.4e38f, outw = -3.4e38f;
            int ine = -1, oute = -1;
            for (int c = 0; c < clen; c++) {
                const int v = s_cyc[c];
                const float sv = S[v * NLEN + node];
                if (sv > inw) { inw = sv; ine = v; }
                const float so = cw + S[node * NLEN + v] - S[s_par[v] * NLEN + v];
                if (so > outw) { outw = so; oute = v; }
            }
            S[rep * NLEN + node] = inw;
            OI[rep * NLEN + node] = OI[ine * NLEN + node];
            OO[rep * NLEN + node] = OO[ine * NLEN + node];
            S[node * NLEN + rep] = outw;
            OO[node * NLEN + rep] = OO[node * NLEN + oute];
            OI[node * NLEN + rep] = OI[node * NLEN + oute];
        }
        __syncthreads();

        const int d = s_depth;
        g_stk_par[((size_t)b * MAXF + d) * NLEN + tid] = (unsigned char)s_par[tid];
        if (tid < clen) g_stk_cyc[((size_t)b * MAXF + d) * NLEN + tid] = (unsigned char)s_cyc[tid];
        __syncthreads();
        if (tid == 0) {
            g_stk_clen[b * MAXF + d] = clen;
            for (int c = 0; c < clen; c++) {
                const int v = s_cyc[c];
                const unsigned long long a0 = s_repA[v], a1 = s_repB[v];
                const size_t ci = (((size_t)b * MAXF + d) * NLEN + c) * 2;
                g_stk_cons[ci] = a0; g_stk_cons[ci + 1] = a1;
                if (c > 0) { s_cur[v] = 0; s_repA[rep] |= a0; s_repB[rep] |= a1; }
            }
            s_depth = d + 1;
        }
        __syncthreads();
    }

    if (tid == 0) {
        s_final[0] = -1;
        for (int node = 1; node < NLEN; node++) {
            if (!s_cur[node]) continue;
            const int p = s_par[node];
            s_final[OO[p * NLEN + node]] = OI[p * NLEN + node];
        }
        for (int d = s_depth - 1; d >= 0; d--) {
            const int clen = g_stk_clen[b * MAXF + d];
            const unsigned char* par = &g_stk_par[((size_t)b * MAXF + d) * NLEN];
            const unsigned char* cyc = &g_stk_cyc[((size_t)b * MAXF + d) * NLEN];
            unsigned long long f0 = 0, f1 = 0;
            for (int x = 0; x < NLEN; x++)
                if (s_final[x] != -2) { if (x < 64) f0 |= 1ull << x; else f1 |= 1ull << (x - 64); }
            int key = -1;
            for (int c = 0; c < clen; c++) {
                const size_t ci = (((size_t)b * MAXF + d) * NLEN + c) * 2;
                if ((g_stk_cons[ci] & f0) | (g_stk_cons[ci + 1] & f1)) { key = cyc[c]; break; }
            }
            if (key < 0) continue;
            int prev = par[key];
            while (prev != key) {
                const int pp = par[prev];
                s_final[OO[pp * NLEN + prev]] = OI[pp * NLEN + prev];
                prev = pp;
            }
        }
    }
    __syncthreads();

    if (has_tail) {
        float hv = 0.f, tv = 1.f;
        const int fe = s_final[tid];
        if (fe != -2) {
            hv = (float)fe;
            const int row = (fe < 0) ? (NLEN - 1) : fe;
            tv = (float)g_labelid[(size_t)b * TT + row * NLEN + tid];
        }
        out[(size_t)EN_ELEMS + b * NLEN + tid] = hv;
        out[(size_t)EN_ELEMS + B_ * NLEN + b * NLEN + tid] = tv;
    }
}

// ---------------------------------------------------------------------------
// Launch
// ---------------------------------------------------------------------------
extern "C" void kernel_launch(void* const* d_in, const int* in_sizes, int n_in,
                              void* d_out, int out_size)
{
    const float* X    = (const float*)d_in[0];
    const float* Wha  = (const float*)d_in[1];
    const float* bha  = (const float*)d_in[2];
    const float* Wda  = (const float*)d_in[3];
    const float* bda  = (const float*)d_in[4];
    const float* Uarc = (const float*)d_in[5];
    const float* Whl  = (const float*)d_in[6];
    const float* bhl  = (const float*)d_in[7];
    const float* Wdl  = (const float*)d_in[8];
    const float* bdl  = (const float*)d_in[9];
    const float* Ulab = (const float*)d_in[10];
    float* out = (float*)d_out;

    void* p;
    cudaGetSymbolAddress(&p, g_Wt);   float* Wt   = (float*)p;
    cudaGetSymbolAddress(&p, g_bp);   float* bp   = (float*)p;
    cudaGetSymbolAddress(&p, g_Uat);  float* Uat  = (float*)p;
    cudaGetSymbolAddress(&p, g_Ult);  float* Ult  = (float*)p;
    cudaGetSymbolAddress(&p, g_proj); float* proj = (float*)p;
    cudaGetSymbolAddress(&p, g_marc); float* marc = (float*)p;
    cudaGetSymbolAddress(&p, g_hl);   float* hl   = (float*)p;
    cudaGetSymbolAddress(&p, g_arc);  float* arc  = (float*)p;

    static int init_done = 0;
    if (!init_done) {
        cudaFuncSetAttribute(k_mma, cudaFuncAttributeMaxDynamicSharedMemorySize, SMEMSZ);
        init_done = 1;
    }
    const int has_tail = (out_size >= EN_ELEMS + 2 * B_ * T_);

    k_prep_W<<<(NP * D_ + 255) / 256, 256>>>(Wha, Wda, Whl, Wdl, bha, bda, bhl, bdl);
    k_prep_Ua<<<(A_ * A_ + 255) / 256, 256>>>(Uarc);
    k_prep_Ul<<<(L_ * R_ * R_ + 255) / 256, 256>>>(Ulab);

    // proj = elu(X @ Wt^T + b): [4096,1280], K=768
    k_mma<<<dim3(NP / 128, BT / 128, 1), 256, SMEMSZ>>>(
        X, 0, D_, Wt, 0, D_, proj, 0, NP, bp, D_, 1, 0);
    // marc = harc @ Uat^T: [4096,512], K=512
    k_mma<<<dim3(A_ / 128, BT / 128, 1), 256, SMEMSZ>>>(
        proj + OFF_HARC, 0, NP, Uat, 0, A_, marc, 0, A_, (float*)0, A_, 0, 0);
    // arc[b] = marc[b] @ darc[b]^T: K=512
    k_mma<<<dim3(1, 1, B_), 256, SMEMSZ>>>(
        marc, (long long)T_ * A_, A_, proj + OFF_DARC, (long long)T_ * NP, NP,
        arc, (long long)TT, T_, (float*)0, A_, 0, 0);
    // hl[b,l] = hlab[b] @ Ult[l]^T: K=128, z = b*50+l
    k_mma<<<dim3(1, 1, B_ * L_), 256, SMEMSZ>>>(
        proj + OFF_HLAB, (long long)T_ * NP, NP, Ult, (long long)R_ * R_, R_,
        hl, (long long)TT, T_, (float*)0, R_, 0, 1);
    // labsc[b,l] = hl[b,l] @ dlab[b]^T -> straight into out (overwritten in-place by k_energy)
    k_mma<<<dim3(1, 1, B_ * L_), 256, SMEMSZ>>>(
        hl, (long long)TT, T_, proj + OFF_DLAB, (long long)T_ * NP, NP,
        out, (long long)TT, T_, (float*)0, R_, 0, 2);

    k_norm_arc<<<B_, T_>>>();
    k_energy<<<B_ * T_, T_>>>(out);
    k_mst<<<B_, NLEN>>>(out, has_tail);
}